// round 4
// baseline (speedup 1.0000x reference)
#include <cuda_runtime.h>
#include <math.h>

// a = (K/2) * w = (K/2) * 2*pi*gf*F = pi * F * K * gf,  F=1000, K=1/44100
#define A_PER_GF 0.07123792533241012f   // pi*1000/44100

struct Coef {
    float p[16];   // P = 2*inv(I - kA/2) - I, row-major
    float b[4];    // b = inv(I - kA/2) @ (k/2 * Bv)
    float gain;
};

static __device__ __forceinline__ Coef make_coef(float gf, float gr, float gain_p) {
    // M = I - (k/2)A = [[d,0,0,c],[-s,d,0,0],[0,-s,d,0],[0,0,-s,d]]
    float a = A_PER_GF * gf;
    float s = a;
    float d = 1.0f + a;
    float c = 2.0f * a * gr;          // (k/2)*4*w*gr*R, R=0.5

    float d2 = d * d, d3 = d2 * d;
    float s2 = s * s, s3 = s2 * s;
    float invDet = 1.0f / (d3 * d + c * s3);
    float invd = 1.0f / d;

    float inv[4][4];
    inv[0][0] =  d3 * invDet;
    inv[0][1] = -c * s2 * invDet;
    inv[0][2] = -c * s * d * invDet;
    inv[0][3] = -c * d2 * invDet;
#pragma unroll
    for (int i = 1; i < 4; i++)
#pragma unroll
        for (int j = 0; j < 4; j++)
            inv[i][j] = (s * inv[i - 1][j] + ((i == j) ? 1.0f : 0.0f)) * invd;

    Coef k;
#pragma unroll
    for (int i = 0; i < 4; i++) {
#pragma unroll
        for (int j = 0; j < 4; j++)
            k.p[i * 4 + j] = 2.0f * inv[i][j] - ((i == j) ? 1.0f : 0.0f);
        k.b[i] = a * inv[i][0];       // Inv @ ((k/2)*w * e0)
    }
    k.gain = gain_p;
    return k;
}

static __device__ __forceinline__ float4 step(const Coef& k, float4 x, float us,
                                              float& y_out) {
    float x0 = fmaf(k.p[0],  x.x, fmaf(k.p[1],  x.y, fmaf(k.p[2],  x.z, fmaf(k.p[3],  x.w, k.b[0] * us))));
    float x1 = fmaf(k.p[4],  x.x, fmaf(k.p[5],  x.y, fmaf(k.p[6],  x.z, fmaf(k.p[7],  x.w, k.b[1] * us))));
    float x2 = fmaf(k.p[8],  x.x, fmaf(k.p[9],  x.y, fmaf(k.p[10], x.z, fmaf(k.p[11], x.w, k.b[2] * us))));
    float x3 = fmaf(k.p[12], x.x, fmaf(k.p[13], x.y, fmaf(k.p[14], x.z, fmaf(k.p[15], x.w, k.b[3] * us))));
    y_out = k.gain * x3;
    return make_float4(x0, x1, x2, x3);
}

// Vectorized: each thread handles 4 consecutive batch elements (B % 4 == 0).
// All global traffic uses streaming (evict-first) cache policy: every byte is
// read-once / write-once, so L2 retention only causes thrash.
__global__ __launch_bounds__(256) void moog_cell_v4_kernel(
    const float4* __restrict__ u_n,     // B/4 float4
    const float4* __restrict__ x_n1,    // B float4 (one per element)
    const float4* __restrict__ u_n1,    // B/4 float4
    float* __restrict__ out,            // [y (B) | x (4B) | u (B)]
    int B,
    const float* __restrict__ gf_p,
    const float* __restrict__ gr_p,
    const float* __restrict__ gain_pp)
{
    const Coef k = make_coef(__ldg(gf_p), __ldg(gr_p), __ldg(gain_pp));

    int n4 = B >> 2;
    int t = blockIdx.x * blockDim.x + threadIdx.x;
    if (t >= n4) return;

    float4 u4  = __ldcs(&u_n[t]);
    float4 u14 = __ldcs(&u_n1[t]);
    float4 xa = __ldcs(&x_n1[4 * t + 0]);
    float4 xb = __ldcs(&x_n1[4 * t + 1]);
    float4 xc = __ldcs(&x_n1[4 * t + 2]);
    float4 xd = __ldcs(&x_n1[4 * t + 3]);

    float4 y4;
    float4 ra = step(k, xa, u4.x + u14.x, y4.x);
    float4 rb = step(k, xb, u4.y + u14.y, y4.y);
    float4 rc = step(k, xc, u4.z + u14.z, y4.z);
    float4 rd = step(k, xd, u4.w + u14.w, y4.w);

    float4* ybase = reinterpret_cast<float4*>(out);
    float4* xbase = reinterpret_cast<float4*>(out + B);
    float4* ubase = reinterpret_cast<float4*>(out + 5 * (size_t)B);

    __stcs(&ybase[t], y4);
    __stcs(&xbase[4 * t + 0], ra);
    __stcs(&xbase[4 * t + 1], rb);
    __stcs(&xbase[4 * t + 2], rc);
    __stcs(&xbase[4 * t + 3], rd);
    __stcs(&ubase[t], u4);    // u_n passthrough
}

// Scalar fallback for B % 4 != 0 (not expected for this problem).
__global__ __launch_bounds__(256) void moog_cell_scalar_kernel(
    const float* __restrict__ u_n,
    const float4* __restrict__ x_n1,
    const float* __restrict__ u_n1,
    float* __restrict__ out,
    int B,
    const float* __restrict__ gf_p,
    const float* __restrict__ gr_p,
    const float* __restrict__ gain_pp)
{
    const Coef k = make_coef(__ldg(gf_p), __ldg(gr_p), __ldg(gain_pp));
    int i = blockIdx.x * blockDim.x + threadIdx.x;
    if (i >= B) return;
    float u = __ldcs(&u_n[i]);
    float y;
    float4 r = step(k, __ldcs(&x_n1[i]), u + __ldcs(&u_n1[i]), y);
    __stcs(&out[i], y);
    __stcs(&reinterpret_cast<float4*>(out + B)[i], r);
    __stcs(&out[5 * (size_t)B + i], u);
}

extern "C" void kernel_launch(void* const* d_in, const int* in_sizes, int n_in,
                              void* d_out, int out_size) {
    const float* u_n    = (const float*)d_in[0];
    const float4* x_n1  = (const float4*)d_in[1];
    const float* u_n1   = (const float*)d_in[2];
    // scalars are the last three device inputs regardless of batch_size materialization
    const float* gf     = (const float*)d_in[n_in - 3];
    const float* gr     = (const float*)d_in[n_in - 2];
    const float* gain_p = (const float*)d_in[n_in - 1];

    int B = in_sizes[0];
    float* out = (float*)d_out;

    if ((B & 3) == 0) {
        int n4 = B >> 2;
        int threads = 256;
        int blocks = (n4 + threads - 1) / threads;
        moog_cell_v4_kernel<<<blocks, threads>>>(
            (const float4*)u_n, x_n1, (const float4*)u_n1, out, B, gf, gr, gain_p);
    } else {
        int threads = 256;
        int blocks = (B + threads - 1) / threads;
        moog_cell_scalar_kernel<<<blocks, threads>>>(
            u_n, x_n1, u_n1, out, B, gf, gr, gain_p);
    }
}

// round 5
// speedup vs baseline: 1.0588x; 1.0588x over previous
#include <cuda_runtime.h>
#include <math.h>

// a = (K/2)*w = pi*F*K*gf, F=1000, K=1/44100
#define A_PER_GF 0.07123792533241012f   // pi*1000/44100

struct Coef {
    float p[16];   // P = 2*inv(I - kA/2) - I, row-major
    float b[4];    // b = inv(I - kA/2) @ (k/2 * Bv)
    float gain;
};

static __device__ __forceinline__ Coef make_coef(float gf, float gr, float gain_p) {
    // M = I - (k/2)A = [[d,0,0,c],[-s,d,0,0],[0,-s,d,0],[0,0,-s,d]]
    float a = A_PER_GF * gf;
    float s = a;
    float d = 1.0f + a;
    float c = 2.0f * a * gr;

    float d2 = d * d, d3 = d2 * d;
    float s2 = s * s, s3 = s2 * s;
    float invDet = 1.0f / (d3 * d + c * s3);
    float invd = 1.0f / d;

    float inv[4][4];
    inv[0][0] =  d3 * invDet;
    inv[0][1] = -c * s2 * invDet;
    inv[0][2] = -c * s * d * invDet;
    inv[0][3] = -c * d2 * invDet;
#pragma unroll
    for (int i = 1; i < 4; i++)
#pragma unroll
        for (int j = 0; j < 4; j++)
            inv[i][j] = (s * inv[i - 1][j] + ((i == j) ? 1.0f : 0.0f)) * invd;

    Coef k;
#pragma unroll
    for (int i = 0; i < 4; i++) {
#pragma unroll
        for (int j = 0; j < 4; j++)
            k.p[i * 4 + j] = 2.0f * inv[i][j] - ((i == j) ? 1.0f : 0.0f);
        k.b[i] = a * inv[i][0];
    }
    k.gain = gain_p;
    return k;
}

static __device__ __forceinline__ float4 step(const Coef& k, float4 x, float us,
                                              float& y_out) {
    float x0 = fmaf(k.p[0],  x.x, fmaf(k.p[1],  x.y, fmaf(k.p[2],  x.z, fmaf(k.p[3],  x.w, k.b[0] * us))));
    float x1 = fmaf(k.p[4],  x.x, fmaf(k.p[5],  x.y, fmaf(k.p[6],  x.z, fmaf(k.p[7],  x.w, k.b[1] * us))));
    float x2 = fmaf(k.p[8],  x.x, fmaf(k.p[9],  x.y, fmaf(k.p[10], x.z, fmaf(k.p[11], x.w, k.b[2] * us))));
    float x3 = fmaf(k.p[12], x.x, fmaf(k.p[13], x.y, fmaf(k.p[14], x.z, fmaf(k.p[15], x.w, k.b[3] * us))));
    y_out = k.gain * x3;
    return make_float4(x0, x1, x2, x3);
}

// Two elements per thread: all traffic is 128-bit (u/u1/y as float2-pairs packed
// into float4 at half rate handled by pairing two elements per thread).
// Per thread: loads = u2(float2->use float2? no: use float2 via float4 at
// element-pair granularity) — we use: 1x float2 u, 1x float2 u1, 2x float4 x.
// To keep everything 128-bit, u/u1/y/u-out are handled as float2 (64-bit) —
// still fully coalesced (8B per lane = 256B per warp segment).
__global__ __launch_bounds__(256) void moog_cell_v2_kernel(
    const float2* __restrict__ u_n,     // B/2 float2
    const float4* __restrict__ x_n1,    // B float4
    const float2* __restrict__ u_n1,    // B/2 float2
    float* __restrict__ out,            // [y (B) | x (4B) | u (B)]
    int B,
    const float* __restrict__ gf_p,
    const float* __restrict__ gr_p,
    const float* __restrict__ gain_pp)
{
    const Coef k = make_coef(__ldg(gf_p), __ldg(gr_p), __ldg(gain_pp));

    int n2 = B >> 1;
    int t = blockIdx.x * blockDim.x + threadIdx.x;
    if (t >= n2) return;

    float2 u2  = u_n[t];
    float2 u12 = u_n1[t];
    float4 xa = x_n1[2 * t + 0];
    float4 xb = x_n1[2 * t + 1];

    float2 y2;
    float4 ra = step(k, xa, u2.x + u12.x, y2.x);
    float4 rb = step(k, xb, u2.y + u12.y, y2.y);

    float2* ybase = reinterpret_cast<float2*>(out);
    float4* xbase = reinterpret_cast<float4*>(out + B);
    float2* ubase = reinterpret_cast<float2*>(out + 5 * (size_t)B);

    ybase[t] = y2;
    xbase[2 * t + 0] = ra;
    xbase[2 * t + 1] = rb;
    ubase[t] = u2;   // u_n passthrough
}

// Scalar fallback for odd B (not expected).
__global__ __launch_bounds__(256) void moog_cell_scalar_kernel(
    const float* __restrict__ u_n,
    const float4* __restrict__ x_n1,
    const float* __restrict__ u_n1,
    float* __restrict__ out,
    int B,
    const float* __restrict__ gf_p,
    const float* __restrict__ gr_p,
    const float* __restrict__ gain_pp)
{
    const Coef k = make_coef(__ldg(gf_p), __ldg(gr_p), __ldg(gain_pp));
    int i = blockIdx.x * blockDim.x + threadIdx.x;
    if (i >= B) return;
    float u = u_n[i];
    float y;
    float4 r = step(k, x_n1[i], u + u_n1[i], y);
    out[i] = y;
    reinterpret_cast<float4*>(out + B)[i] = r;
    out[5 * (size_t)B + i] = u;
}

extern "C" void kernel_launch(void* const* d_in, const int* in_sizes, int n_in,
                              void* d_out, int out_size) {
    const float* u_n    = (const float*)d_in[0];
    const float4* x_n1  = (const float4*)d_in[1];
    const float* u_n1   = (const float*)d_in[2];
    // scalars are the last three device inputs regardless of batch_size materialization
    const float* gf     = (const float*)d_in[n_in - 3];
    const float* gr     = (const float*)d_in[n_in - 2];
    const float* gain_p = (const float*)d_in[n_in - 1];

    int B = in_sizes[0];
    float* out = (float*)d_out;

    if ((B & 1) == 0) {
        int n2 = B >> 1;
        int threads = 256;
        int blocks = (n2 + threads - 1) / threads;
        moog_cell_v2_kernel<<<blocks, threads>>>(
            (const float2*)u_n, x_n1, (const float2*)u_n1, out, B, gf, gr, gain_p);
    } else {
        int threads = 256;
        int blocks = (B + threads - 1) / threads;
        moog_cell_scalar_kernel<<<blocks, threads>>>(
            u_n, x_n1, u_n1, out, B, gf, gr, gain_p);
    }
}